// round 7
// baseline (speedup 1.0000x reference)
#include <cuda_runtime.h>

// ---------------- problem constants ----------------
#define KCLS 20
#define HH   480
#define WW   640
#define NPIX (HH * WW)           // 307200
#define NBATCH 4
#define FC   512
#define FH   30
#define FW   40
#define FHW  (FH * FW)           // 1200
#define NBOX 5
#define COUNT_THRESH 10000
#define XELEMS ((long long)(NBOX + 1) * NBATCH * FC * FHW)   // 14,745,600

// ---------------- device scratch (zero-init; every launch leaves it reset) -----
__device__ int      g_cnt[KCLS];        // exact pixel counts
__device__ unsigned g_xlo[KCLS];        // coarse-x (x>>4) presence bits 0..31
__device__ unsigned g_xhi[KCLS];        // coarse-x bits 32..39
__device__ unsigned g_ym[KCLS];         // coarse-y (y>>4) presence bits 0..29
__device__ unsigned g_done;             // stats completion counter
__device__ int      g_node[NBOX][4];    // x0, y0, cw, ch (feature coords)

// ---------------- kernel 1: argmax(K=20) of batch 3 + stats + tail selection ---
__global__ void k_stats(const float* __restrict__ seg,
                        float* __restrict__ out, const float* __restrict__ pool,
                        int pool_n, int x_off) {
    __shared__ int      s_cnt[KCLS];
    __shared__ unsigned s_xlo[KCLS], s_xhi[KCLS], s_ym[KCLS];
    __shared__ int      s_last;
    int t = threadIdx.x;
    if (t < KCLS) { s_cnt[t] = 0; s_xlo[t] = 0; s_xhi[t] = 0; s_ym[t] = 0; }
    __syncthreads();

    int p4 = blockIdx.x * blockDim.x + t;           // quad-pixel index
    const float4* base = (const float4*)(seg + (long long)3 * KCLS * NPIX);

    float b0 = -1e30f, b1 = -1e30f, b2 = -1e30f, b3 = -1e30f;
    int   k0 = 0, k1 = 0, k2 = 0, k3 = 0;
#pragma unroll
    for (int k = 0; k < KCLS; k++) {
        float4 v = __ldg(base + k * (NPIX / 4) + p4);
        if (v.x > b0) { b0 = v.x; k0 = k; }
        if (v.y > b1) { b1 = v.y; k1 = k; }
        if (v.z > b2) { b2 = v.z; k2 = k; }
        if (v.w > b3) { b3 = v.w; k3 = k; }
    }

    int y  = p4 / (WW / 4);                 // warp-uniform (32 | 160 quads/row)
    int xb = (p4 % (WW / 4)) * 4;
    unsigned ybit = 1u << (y >> 4);
    int lane = t & 31;

    int ks[4] = {k0, k1, k2, k3};
#pragma unroll
    for (int i = 0; i < 4; i++) {
        int k  = ks[i];
        int xc = (xb + i) >> 4;             // coarse x, 0..39
        unsigned m   = __match_any_sync(0xffffffffu, k);
        unsigned xlo = (xc < 32) ? (1u << xc) : 0u;
        unsigned xhi = (xc < 32) ? 0u : (1u << (xc - 32));
        xlo = __reduce_or_sync(m, xlo);
        xhi = __reduce_or_sync(m, xhi);
        if (lane == __ffs(m) - 1) {         // one leader per class-group
            atomicAdd(&s_cnt[k], __popc(m));
            atomicOr(&s_xlo[k], xlo);
            if (xhi) atomicOr(&s_xhi[k], xhi);
            atomicOr(&s_ym[k], ybit);
        }
    }
    __syncthreads();

    if (t < KCLS && s_cnt[t] > 0) {
        atomicAdd(&g_cnt[t], s_cnt[t]);
        atomicOr(&g_xlo[t], s_xlo[t]);
        if (s_xhi[t]) atomicOr(&g_xhi[t], s_xhi[t]);
        atomicOr(&g_ym[t], s_ym[t]);
    }
    __syncthreads();

    if (t == 0) {
        __threadfence();
        unsigned done = atomicAdd(&g_done, 1u);
        s_last = (done == gridDim.x - 1) ? 1 : 0;
    }
    __syncthreads();
    if (!s_last) return;

    // ---------- tail block: selection + pool/scalar outputs ----------
    if (t == 0) {
        int cand[KCLS], ccnt[KCLS];
        int m = 0, first_seen = -1;
        for (int k = 0; k < KCLS; k++) {
            int c = *(volatile int*)&g_cnt[k];
            if (c > 0) {
                if (first_seen < 0) first_seen = k;      // np.unique()[1:] drop
                else { cand[m] = k; ccnt[m] = c; m++; }
            }
        }
        bool used[KCLS];
        for (int i = 0; i < m; i++) used[i] = false;
        int selb[NBOX - 2];
        int selcnt = 0;
        for (int r = 0; r < m && selcnt < NBOX - 2; r++) {
            int best = -1;
            for (int j = 0; j < m; j++)
                if (!used[j] && (best < 0 || ccnt[j] > ccnt[best])) best = j;
            used[best] = true;
            if (ccnt[best] > COUNT_THRESH) selb[selcnt++] = cand[best];
        }
        for (int i = 0; i < selcnt; i++) {
            int k = selb[i];
            unsigned xlo = *(volatile unsigned*)&g_xlo[k];
            unsigned xhi = *(volatile unsigned*)&g_xhi[k];
            unsigned ym  = *(volatile unsigned*)&g_ym[k];
            unsigned long long x64 = ((unsigned long long)xhi << 32) | xlo;
            int x0 = __ffsll(x64) - 1;
            int x1 = 63 - __clzll(x64);
            int y0 = __ffs(ym) - 1;
            int y1 = 31 - __clz(ym);
            int cw = x1 - x0; if (cw < 1) cw = 1;
            int ch = y1 - y0; if (ch < 1) ch = 1;
            g_node[i][0] = x0; g_node[i][1] = y0;
            g_node[i][2] = cw; g_node[i][3] = ch;
        }
        const int bb[5][4] = {
            {FW / 4, FH / 4, 3 * FW / 4, 3 * FH / 4},
            {0, 0, FW / 3, FH},
            {0, 0, FW, FH / 3},
            {2 * FW / 3, 0, FW, FH},
            {0, 2 * FH / 3, FW, FH}};
        int need = NBOX - selcnt;
        for (int i = 0; i < need; i++) {
            int x0 = bb[i][0], y0 = bb[i][1];
            g_node[selcnt + i][0] = x0; g_node[selcnt + i][1] = y0;
            g_node[selcnt + i][2] = bb[i][2] - x0;
            g_node[selcnt + i][3] = bb[i][3] - y0;
        }
        if (x_off == pool_n + 2) {
            out[pool_n]     = (float)NBOX;     // 5
            out[pool_n + 1] = (float)NBATCH;   // 4
        }
        g_done = 0;                            // ready for next graph replay
        __threadfence();
    }
    if (x_off >= pool_n)
        for (int i = t; i < pool_n; i += blockDim.x) out[i] = pool[i];
}

// ---------------- kernel 2: crop + bilinear resize via smem, append feat -------
// grid (24, 128), block (20, 15). 4 channels per block.
// o = n*5 + b for o<20 (raw-reshape plane order); o>=20 -> feat copy.
__global__ __launch_bounds__(300) void k_build(float* __restrict__ out_x,
                                               const float* __restrict__ feat) {
    __shared__ float sc[4][FH * FW];          // staged crop, stride 40, 19.2 KB
    int o  = blockIdx.x;
    int c0 = blockIdx.y << 2;
    int tx = threadIdx.x;                     // 0..19
    int ty = threadIdx.y;                     // 0..14

    if (o >= 20) {                            // feat append, float2
        int n   = o - 20;
        int tid = ty * 20 + tx;
        if (o == 20 && blockIdx.y == 0 && tid == 0) {
            // reset stats for the next graph replay (nothing in k_build reads these)
#pragma unroll
            for (int k = 0; k < KCLS; k++) {
                g_cnt[k] = 0; g_xlo[k] = 0; g_xhi[k] = 0; g_ym[k] = 0;
            }
        }
        const float2* src = (const float2*)feat + ((n * FC + c0) * FHW >> 1);
        float2*       dst = (float2*)out_x + ((o * FC + c0) * FHW >> 1);
#pragma unroll
        for (int i = 0; i < 8; i++)
            dst[tid + i * 300] = __ldg(src + tid + i * 300);
        return;
    }

    int n = o / NBOX;
    int b = o - n * NBOX;

    int x0 = g_node[b][0], y0 = g_node[b][1];
    int cw = g_node[b][2], ch = g_node[b][3];

    // stage 4 channels of the crop (coalesced rows)
    {
        int sb = (n * FC + c0) * FHW + y0 * FW + x0;
#pragma unroll
        for (int cc = 0; cc < 4; cc++) {
            const float* src = feat + sb + cc * FHW;
            for (int ry = ty; ry < ch; ry += 15)
                for (int cx = tx; cx < cw; cx += 20)
                    sc[cc][ry * FW + cx] = __ldg(src + ry * FW + cx);
        }
    }

    // interp params in registers
    float sxs = (float)cw / (float)FW;
    float sys = (float)ch / (float)FH;
    int xa0, xb0, xa1, xb1; float fx0, fx1;
    {
        float s = ((float)(2 * tx) + 0.5f) * sxs - 0.5f;
        s = fminf(fmaxf(s, 0.0f), (float)(cw - 1));
        xa0 = (int)s; fx0 = s - (float)xa0; xb0 = min(xa0 + 1, cw - 1);
        s = ((float)(2 * tx + 1) + 0.5f) * sxs - 0.5f;
        s = fminf(fmaxf(s, 0.0f), (float)(cw - 1));
        xa1 = (int)s; fx1 = s - (float)xa1; xb1 = min(xa1 + 1, cw - 1);
    }
    int ry0[2], ry1[2]; float fyv[2];
#pragma unroll
    for (int hh = 0; hh < 2; hh++) {
        float s = ((float)(ty + hh * 15) + 0.5f) * sys - 0.5f;
        s = fminf(fmaxf(s, 0.0f), (float)(ch - 1));
        int ya = (int)s;
        fyv[hh] = s - (float)ya;
        ry0[hh] = ya * FW;
        ry1[hh] = min(ya + 1, ch - 1) * FW;
    }
    __syncthreads();

    int dst_base = (o * FC + c0) * FHW;
#pragma unroll
    for (int cc = 0; cc < 4; cc++) {
        const float* sp = sc[cc];
        float*       dst = out_x + dst_base + cc * FHW;
#pragma unroll
        for (int hh = 0; hh < 2; hh++) {
            const float* r0 = sp + ry0[hh];
            const float* r1 = sp + ry1[hh];
            float fy  = fyv[hh];
            float ofy = 1.0f - fy;
            float t0 = (1.0f - fx0) * r0[xa0] + fx0 * r0[xb0];
            float u0 = (1.0f - fx0) * r1[xa0] + fx0 * r1[xb0];
            float t1 = (1.0f - fx1) * r0[xa1] + fx1 * r0[xb1];
            float u1 = (1.0f - fx1) * r1[xa1] + fx1 * r1[xb1];
            float2 pv;
            pv.x = ofy * t0 + fy * u0;
            pv.y = ofy * t1 + fy * u1;
            ((float2*)(dst + (ty + hh * 15) * FW))[tx] = pv;
        }
    }
}

// ---------------- launcher: 2 kernels only ----------------
extern "C" void kernel_launch(void* const* d_in, const int* in_sizes, int n_in,
                              void* d_out, int out_size) {
    const float* seg  = (const float*)d_in[0];
    const float* feat = (const float*)d_in[1];
    const float* pool = (const float*)d_in[2];
    float* out = (float*)d_out;

    long long x_off_ll = (long long)out_size - XELEMS;
    if (x_off_ll < 0) x_off_ll = 0;
    int x_off = (int)x_off_ll;
    int pool_n = (n_in > 2) ? in_sizes[2] : 0;
    if (pool_n > x_off) pool_n = x_off;

    k_stats<<<NPIX / 4 / 256, 256>>>(seg, out, pool, pool_n, x_off);
    dim3 grid((NBOX + 1) * NBATCH, FC / 4);     // (24, 128)
    dim3 blk(20, 15);
    k_build<<<grid, blk>>>(out + x_off, feat);
}

// round 11
// speedup vs baseline: 1.4396x; 1.4396x over previous
#include <cuda_runtime.h>

// ---------------- problem constants ----------------
#define KCLS 20
#define HH   480
#define WW   640
#define NPIX (HH * WW)           // 307200
#define NBATCH 4
#define FC   512
#define FH   30
#define FW   40
#define FHW  (FH * FW)           // 1200
#define NBOX 5
#define COUNT_THRESH 10000
#define XELEMS ((long long)(NBOX + 1) * NBATCH * FC * FHW)   // 14,745,600

// ---------------- device scratch (zero-init is the neutral state) --------------
__device__ int      g_cnt[KCLS];        // exact pixel counts
__device__ unsigned g_xlo[KCLS];        // coarse-x (x>>4) presence bits 0..31
__device__ unsigned g_xhi[KCLS];        // coarse-x bits 32..39
__device__ unsigned g_ym[KCLS];         // coarse-y (y>>4) presence bits 0..29
__device__ int      g_node[NBOX][4];    // x0, y0, cw, ch (feature coords)

// ---------------- kernel 1: argmax(K=20) of batch 3 + per-class stats ----------
// Plain shared atomics (spread addresses), 3 atomics per pixel.
__global__ void k_stats(const float* __restrict__ seg) {
    __shared__ int      s_cnt[KCLS];
    __shared__ unsigned s_xlo[KCLS], s_xhi[KCLS], s_ym[KCLS];
    int t = threadIdx.x;
    if (t < KCLS) { s_cnt[t] = 0; s_xlo[t] = 0; s_xhi[t] = 0; s_ym[t] = 0; }
    __syncthreads();

    int p4 = blockIdx.x * blockDim.x + t;           // quad-pixel index
    const float4* base = (const float4*)(seg + (long long)3 * KCLS * NPIX);

    float b0 = -1e30f, b1 = -1e30f, b2 = -1e30f, b3 = -1e30f;
    int   k0 = 0, k1 = 0, k2 = 0, k3 = 0;
#pragma unroll
    for (int k = 0; k < KCLS; k++) {
        float4 v = __ldg(base + k * (NPIX / 4) + p4);
        if (v.x > b0) { b0 = v.x; k0 = k; }
        if (v.y > b1) { b1 = v.y; k1 = k; }
        if (v.z > b2) { b2 = v.z; k2 = k; }
        if (v.w > b3) { b3 = v.w; k3 = k; }
    }

    int y  = p4 / (WW / 4);
    int xb = (p4 % (WW / 4)) * 4;
    unsigned ybit = 1u << (y >> 4);
    // all 4 pixels of a quad share the same coarse-x cell (xb = 4m -> (4m+3)>>4 == (4m)>>4)
    int xc = xb >> 4;
    unsigned xbit  = (xc < 32) ? (1u << xc) : 0u;
    unsigned xbith = (xc < 32) ? 0u : (1u << (xc - 32));

    int ks[4] = {k0, k1, k2, k3};
#pragma unroll
    for (int i = 0; i < 4; i++) {
        int k = ks[i];
        atomicAdd(&s_cnt[k], 1);
        if (xbit) atomicOr(&s_xlo[k], xbit);
        else      atomicOr(&s_xhi[k], xbith);
        atomicOr(&s_ym[k], ybit);
    }
    __syncthreads();

    if (t < KCLS && s_cnt[t] > 0) {
        atomicAdd(&g_cnt[t], s_cnt[t]);
        atomicOr(&g_xlo[t], s_xlo[t]);
        if (s_xhi[t]) atomicOr(&g_xhi[t], s_xhi[t]);
        atomicOr(&g_ym[t], s_ym[t]);
    }
}

// ---------------- kernel 2: selection + pool/scalars + stat reset --------------
__global__ void k_select(float* __restrict__ out, const float* __restrict__ pool,
                         int pool_n, int x_off) {
    int t = threadIdx.x;

    if (t == 0) {
        int cand[KCLS], ccnt[KCLS];
        int m = 0, first_seen = -1;
        for (int k = 0; k < KCLS; k++) {
            if (g_cnt[k] > 0) {
                if (first_seen < 0) first_seen = k;      // np.unique()[1:] drop
                else { cand[m] = k; ccnt[m] = g_cnt[k]; m++; }
            }
        }
        bool used[KCLS];
        for (int i = 0; i < m; i++) used[i] = false;
        int selb[NBOX - 2];
        int selcnt = 0;
        for (int r = 0; r < m && selcnt < NBOX - 2; r++) {
            int best = -1;
            for (int j = 0; j < m; j++)
                if (!used[j] && (best < 0 || ccnt[j] > ccnt[best])) best = j;
            used[best] = true;
            if (ccnt[best] > COUNT_THRESH) selb[selcnt++] = cand[best];
        }
        for (int i = 0; i < selcnt; i++) {
            int k = selb[i];
            unsigned long long x64 = ((unsigned long long)g_xhi[k] << 32) | g_xlo[k];
            unsigned ym = g_ym[k];
            int x0 = __ffsll(x64) - 1;
            int x1 = 63 - __clzll(x64);
            int y0 = __ffs(ym) - 1;
            int y1 = 31 - __clz(ym);
            int cw = x1 - x0; if (cw < 1) cw = 1;
            int ch = y1 - y0; if (ch < 1) ch = 1;
            g_node[i][0] = x0; g_node[i][1] = y0;
            g_node[i][2] = cw; g_node[i][3] = ch;
        }
        const int bb[5][4] = {
            {FW / 4, FH / 4, 3 * FW / 4, 3 * FH / 4},
            {0, 0, FW / 3, FH},
            {0, 0, FW, FH / 3},
            {2 * FW / 3, 0, FW, FH},
            {0, 2 * FH / 3, FW, FH}};
        int need = NBOX - selcnt;
        for (int i = 0; i < need; i++) {
            int x0 = bb[i][0], y0 = bb[i][1];
            g_node[selcnt + i][0] = x0; g_node[selcnt + i][1] = y0;
            g_node[selcnt + i][2] = bb[i][2] - x0;
            g_node[selcnt + i][3] = bb[i][3] - y0;
        }
        if (x_off == pool_n + 2) {
            out[pool_n]     = (float)NBOX;     // 5
            out[pool_n + 1] = (float)NBATCH;   // 4
        }
    }

    // ORDER FIX: selection must fully read the stats before anyone resets them.
    __syncthreads();

    // reset stats to neutral (zero) for the next graph replay
    if (t < KCLS) {
        g_cnt[t] = 0; g_xlo[t] = 0; g_xhi[t] = 0; g_ym[t] = 0;
    }
    // pool_x copy
    if (x_off >= pool_n)
        for (int i = t; i < pool_n; i += blockDim.x) out[i] = pool[i];
}

// ---------------- kernel 3: crop + bilinear resize via smem, append feat -------
// grid (24, 128), block (20, 15). 4 channels per block.
// Staging is a FIXED-trip, clamped, coalesced copy (no data-dependent bounds).
__global__ __launch_bounds__(300) void k_build(float* __restrict__ out_x,
                                               const float* __restrict__ feat) {
    __shared__ float sc[4][FH * FW];          // 19.2 KB
    int o  = blockIdx.x;
    int c0 = blockIdx.y << 2;
    int tx = threadIdx.x;                     // 0..19
    int ty = threadIdx.y;                     // 0..14
    int tid = ty * 20 + tx;                   // 0..299

    if (o >= 20) {                            // feat append, float2
        int n = o - 20;
        const float2* src = (const float2*)feat + ((n * FC + c0) * FHW >> 1);
        float2*       dst = (float2*)out_x + ((o * FC + c0) * FHW >> 1);
#pragma unroll
        for (int i = 0; i < 8; i++)
            dst[tid + i * 300] = __ldg(src + tid + i * 300);
        return;
    }

    int n = o / NBOX;
    int b = o - n * NBOX;

    int x0 = g_node[b][0], y0 = g_node[b][1];
    int cw = g_node[b][2], ch = g_node[b][3];

    // ---- stage 4 channels: fixed 4 iters/channel, clamped source, coalesced ----
    {
        int sb = (n * FC + c0) * FHW + y0 * FW + x0;
        int che = ch - 1, cwe = cw - 1;
#pragma unroll
        for (int cc = 0; cc < 4; cc++) {
            const float* src = feat + sb + cc * FHW;
#pragma unroll
            for (int j = 0; j < 4; j++) {
                int e  = tid + j * 300;       // 0..1199
                int ry = e / 40;
                int cx = e - ry * 40;
                int rys = min(ry, che);
                int cxs = min(cx, cwe);
                sc[cc][e] = __ldg(src + rys * FW + cxs);
            }
        }
    }

    // ---- interp params in registers ----
    float sxs = (float)cw / (float)FW;
    float sys = (float)ch / (float)FH;
    int xa0, xb0, xa1, xb1; float fx0, fx1;
    {
        float s = ((float)(2 * tx) + 0.5f) * sxs - 0.5f;
        s = fminf(fmaxf(s, 0.0f), (float)(cw - 1));
        xa0 = (int)s; fx0 = s - (float)xa0; xb0 = min(xa0 + 1, cw - 1);
        s = ((float)(2 * tx + 1) + 0.5f) * sxs - 0.5f;
        s = fminf(fmaxf(s, 0.0f), (float)(cw - 1));
        xa1 = (int)s; fx1 = s - (float)xa1; xb1 = min(xa1 + 1, cw - 1);
    }
    int ry0[2], ry1[2]; float fyv[2];
#pragma unroll
    for (int hh = 0; hh < 2; hh++) {
        float s = ((float)(ty + hh * 15) + 0.5f) * sys - 0.5f;
        s = fminf(fmaxf(s, 0.0f), (float)(ch - 1));
        int ya = (int)s;
        fyv[hh] = s - (float)ya;
        ry0[hh] = ya * FW;
        ry1[hh] = min(ya + 1, ch - 1) * FW;
    }
    __syncthreads();

    int dst_base = (o * FC + c0) * FHW;
#pragma unroll
    for (int cc = 0; cc < 4; cc++) {
        const float* sp  = sc[cc];
        float*       dst = out_x + dst_base + cc * FHW;
#pragma unroll
        for (int hh = 0; hh < 2; hh++) {
            const float* r0 = sp + ry0[hh];
            const float* r1 = sp + ry1[hh];
            float fy  = fyv[hh];
            float ofy = 1.0f - fy;
            float t0 = (1.0f - fx0) * r0[xa0] + fx0 * r0[xb0];
            float u0 = (1.0f - fx0) * r1[xa0] + fx0 * r1[xb0];
            float t1 = (1.0f - fx1) * r0[xa1] + fx1 * r0[xb1];
            float u1 = (1.0f - fx1) * r1[xa1] + fx1 * r1[xb1];
            float2 pv;
            pv.x = ofy * t0 + fy * u0;
            pv.y = ofy * t1 + fy * u1;
            ((float2*)(dst + (ty + hh * 15) * FW))[tx] = pv;
        }
    }
}

// ---------------- launcher: 3 kernels ----------------
extern "C" void kernel_launch(void* const* d_in, const int* in_sizes, int n_in,
                              void* d_out, int out_size) {
    const float* seg  = (const float*)d_in[0];
    const float* feat = (const float*)d_in[1];
    const float* pool = (const float*)d_in[2];
    float* out = (float*)d_out;

    long long x_off_ll = (long long)out_size - XELEMS;
    if (x_off_ll < 0) x_off_ll = 0;
    int x_off = (int)x_off_ll;
    int pool_n = (n_in > 2) ? in_sizes[2] : 0;
    if (pool_n > x_off) pool_n = x_off;

    k_stats<<<NPIX / 4 / 256, 256>>>(seg);
    k_select<<<1, 256>>>(out, pool, pool_n, x_off);
    dim3 grid((NBOX + 1) * NBATCH, FC / 4);     // (24, 128)
    dim3 blk(20, 15);
    k_build<<<grid, blk>>>(out + x_off, feat);
}